// round 8
// baseline (speedup 1.0000x reference)
#include <cuda_runtime.h>
#include <cuda_bf16.h>

// CrossNet: B=500000, D=128, L=4.   out = alpha_L * x0 + beta_L
//   d_l = w_l·x0 ; alpha_{l+1} = alpha_l*(1+d_l) + c_l ; c_l = w_l·beta_l
//
// R8: occupancy play. Row-independent constants (beta_L, c_l) are computed by
// a one-warp setup kernel into __device__ globals, removing the per-warp
// prologue. Main kernel: 16-lane teams, weights in SMEM, 2 rows/iter x 4,
// __launch_bounds__(256,5) -> <=48 regs -> 5 blocks/SM (62.5% occ) vs R7's
// 4 blocks/41.6% (latency-bound: DRAM 75%, L1 78%, issue 40%).

#define CN_L  4
#define CN_D  128

__device__ float4 g_beta[32];   // beta_L as float4[32]
__device__ float  g_c[CN_L];    // c_l scalars

// ---- setup: single warp computes beta_L and c_l ----
__global__ void crossnet_setup(const float4* __restrict__ w4,
                               const float4* __restrict__ b4)
{
    const int lane = threadIdx.x & 31;
    float4 bt = make_float4(0.f, 0.f, 0.f, 0.f);   // lane's 4 cols of beta
#pragma unroll
    for (int l = 0; l < CN_L; ++l) {
        const float4 wl = w4[l * 32 + lane];
        float p = wl.x * bt.x;
        p = fmaf(wl.y, bt.y, p);
        p = fmaf(wl.z, bt.z, p);
        p = fmaf(wl.w, bt.w, p);
#pragma unroll
        for (int off = 16; off > 0; off >>= 1)
            p += __shfl_xor_sync(0xffffffffu, p, off);
        if (lane == 0) g_c[l] = p;
        const float4 bl = b4[l * 32 + lane];
        bt.x += bl.x; bt.y += bl.y; bt.z += bl.z; bt.w += bl.w;
    }
    g_beta[lane] = bt;
}

// ---- main kernel ----
__global__ __launch_bounds__(256, 5) void crossnet_kernel(
    const float4* __restrict__ x,     // inputs  [B,128] as float4 [B,32]
    const float4* __restrict__ w4,    // kernels [L,128] as float4
    float4*       __restrict__ out,
    int B)
{
    __shared__ float4 ws[CN_L * 32];

    const int tid = threadIdx.x;
    if (tid < CN_L * 32) ws[tid] = w4[tid];
    __syncthreads();

    const int warp = (blockIdx.x * blockDim.x + tid) >> 5;
    const int lane = tid & 31;
    const int sub  = lane >> 4;     // which of the warp's 2 concurrent rows
    const int li   = lane & 15;     // lane within 16-lane row team

    const long long row0 = (long long)warp * 8;
    if (row0 >= B) return;

    // loop-invariant constants (uniform / per-lane loads, L2-resident)
    const float4 bt0 = __ldg(&g_beta[li]);
    const float4 bt1 = __ldg(&g_beta[16 + li]);
    float c[CN_L];
#pragma unroll
    for (int l = 0; l < CN_L; ++l) c[l] = __ldg(&g_c[l]);

#pragma unroll 1
    for (int it = 0; it < 4; ++it) {
        const long long r = row0 + it * 2 + sub;
        const bool ok = r < B;

        float4 x0 = ok ? __ldcs(&x[r * 32 + li])      : make_float4(0,0,0,0);
        float4 x1 = ok ? __ldcs(&x[r * 32 + 16 + li]) : make_float4(0,0,0,0);

        // partial dots d_l = w_l · x0 over this lane's 8 cols (weights: smem)
        float p[CN_L];
#pragma unroll
        for (int l = 0; l < CN_L; ++l) {
            const float4 w0 = ws[l * 32 + li];
            const float4 w1 = ws[l * 32 + 16 + li];
            float q;
            q = w0.x * x0.x;
            q = fmaf(w0.y, x0.y, q);
            q = fmaf(w0.z, x0.z, q);
            q = fmaf(w0.w, x0.w, q);
            q = fmaf(w1.x, x1.x, q);
            q = fmaf(w1.y, x1.y, q);
            q = fmaf(w1.z, x1.z, q);
            q = fmaf(w1.w, x1.w, q);
            p[l] = q;
        }
        // 4-level butterfly within 16-lane teams (one SHFL serves both rows)
#pragma unroll
        for (int off = 1; off < 16; off <<= 1) {
#pragma unroll
            for (int l = 0; l < CN_L; ++l)
                p[l] += __shfl_xor_sync(0xffffffffu, p[l], off);
        }

        // scalar alpha recurrence
        float a = 1.0f;
#pragma unroll
        for (int l = 0; l < CN_L; ++l)
            a = fmaf(a, p[l], a + c[l]);

        if (ok) {
            float4 o;
            o.x = fmaf(x0.x, a, bt0.x); o.y = fmaf(x0.y, a, bt0.y);
            o.z = fmaf(x0.z, a, bt0.z); o.w = fmaf(x0.w, a, bt0.w);
            __stcs(&out[r * 32 + li], o);
            o.x = fmaf(x1.x, a, bt1.x); o.y = fmaf(x1.y, a, bt1.y);
            o.z = fmaf(x1.z, a, bt1.z); o.w = fmaf(x1.w, a, bt1.w);
            __stcs(&out[r * 32 + 16 + li], o);
        }
    }
}

extern "C" void kernel_launch(void* const* d_in, const int* in_sizes, int n_in,
                              void* d_out, int out_size)
{
    const float* x = (const float*)d_in[0];   // inputs  [B,128]
    const float* w = (const float*)d_in[1];   // kernels [L,128,1]
    const float* b = (const float*)d_in[2];   // biases  [L,128,1]
    float* out = (float*)d_out;

    const int B = in_sizes[0] / CN_D;                       // 500000

    crossnet_setup<<<1, 32>>>(
        reinterpret_cast<const float4*>(w),
        reinterpret_cast<const float4*>(b));

    const long long warps_needed = ((long long)B + 7) / 8;  // 62500
    const int warps_per_block = 256 / 32;
    const int grid = (int)((warps_needed + warps_per_block - 1) / warps_per_block);

    crossnet_kernel<<<grid, 256>>>(
        reinterpret_cast<const float4*>(x),
        reinterpret_cast<const float4*>(w),
        reinterpret_cast<float4*>(out), B);
}

// round 9
// speedup vs baseline: 1.0285x; 1.0285x over previous
#include <cuda_runtime.h>
#include <cuda_bf16.h>

// CrossNet: B=500000, D=128, L=4.   out = alpha_L * x0 + beta_L
//   d_l = w_l·x0 ; alpha_{l+1} = alpha_l*(1+d_l) + c_l ; c_l = w_l·beta_l
//
// R9: 8-lane row teams (3-level butterfly, one warp SHFL serves 4 rows =
// 3 SHFL/row), weights+beta+c in SMEM (computed by warp 0 per block), 8 rows
// per iteration front-batched (8 outstanding LDG.128 per lane -> 256 in-flight
// loads/SM at 4 blocks). R8 failed by trading MLP for occupancy; this raises
// MLP 2x over R7 while cutting MIO ops per row.

#define CN_L  4
#define CN_D  128

__global__ __launch_bounds__(256, 4) void crossnet_kernel(
    const float4* __restrict__ x,     // inputs  [B,128] as float4 [B,32]
    const float4* __restrict__ w4,    // kernels [L,128] as float4
    const float4* __restrict__ b4,    // biases
    float4*       __restrict__ out,
    int B)
{
    __shared__ float4 ws[CN_L * 32];  // weights
    __shared__ float4 sbeta[32];      // beta_L
    __shared__ float  sc[CN_L];       // c_l

    const int tid = threadIdx.x;
    if (tid < CN_L * 32) ws[tid] = w4[tid];
    __syncthreads();

    // warp 0: compute beta_L and c_l into smem
    if (tid < 32) {
        const int ln = tid;
        float4 bt = make_float4(0.f, 0.f, 0.f, 0.f);
#pragma unroll
        for (int l = 0; l < CN_L; ++l) {
            const float4 wl = ws[l * 32 + ln];
            float p = wl.x * bt.x;
            p = fmaf(wl.y, bt.y, p);
            p = fmaf(wl.z, bt.z, p);
            p = fmaf(wl.w, bt.w, p);
#pragma unroll
            for (int off = 16; off > 0; off >>= 1)
                p += __shfl_xor_sync(0xffffffffu, p, off);
            if (ln == 0) sc[l] = p;
            const float4 bl = __ldg(&b4[l * 32 + ln]);
            bt.x += bl.x; bt.y += bl.y; bt.z += bl.z; bt.w += bl.w;
        }
        sbeta[ln] = bt;
    }
    __syncthreads();

    const int warp = (blockIdx.x * blockDim.x + tid) >> 5;
    const int lane = tid & 31;
    const int sub  = lane >> 3;     // row within 4-row group (0..3)
    const int li   = lane & 7;      // lane within 8-lane row team

    const long long row0 = (long long)warp * 16;   // 16 rows per warp
    if (row0 >= B) return;

    float c[CN_L];
#pragma unroll
    for (int l = 0; l < CN_L; ++l) c[l] = sc[l];

#pragma unroll 1
    for (int it = 0; it < 2; ++it) {
        const long long rA = row0 + it * 8 + sub;      // group A row
        const long long rB = rA + 4;                   // group B row
        const bool okA = rA < B;
        const bool okB = rB < B;

        // 8 independent LDG.128 per lane, all front-batched
        float4 xa[4], xb[4];
#pragma unroll
        for (int i = 0; i < 4; ++i)
            xa[i] = okA ? __ldcs(&x[rA * 32 + i * 8 + li])
                        : make_float4(0.f, 0.f, 0.f, 0.f);
#pragma unroll
        for (int i = 0; i < 4; ++i)
            xb[i] = okB ? __ldcs(&x[rB * 32 + i * 8 + li])
                        : make_float4(0.f, 0.f, 0.f, 0.f);

        // partial dots over this lane's 16 cols (weights from smem)
        float pa[CN_L], pb[CN_L];
#pragma unroll
        for (int l = 0; l < CN_L; ++l) {
            float qa = 0.f, qb = 0.f;
#pragma unroll
            for (int i = 0; i < 4; ++i) {
                const float4 wv = ws[l * 32 + i * 8 + li];
                qa = fmaf(wv.x, xa[i].x, qa);  qb = fmaf(wv.x, xb[i].x, qb);
                qa = fmaf(wv.y, xa[i].y, qa);  qb = fmaf(wv.y, xb[i].y, qb);
                qa = fmaf(wv.z, xa[i].z, qa);  qb = fmaf(wv.z, xb[i].z, qb);
                qa = fmaf(wv.w, xa[i].w, qa);  qb = fmaf(wv.w, xb[i].w, qb);
            }
            pa[l] = qa; pb[l] = qb;
        }
        // 3-level butterfly within 8-lane teams; each SHFL serves 4 rows
#pragma unroll
        for (int off = 1; off < 8; off <<= 1) {
#pragma unroll
            for (int l = 0; l < CN_L; ++l) {
                pa[l] += __shfl_xor_sync(0xffffffffu, pa[l], off);
                pb[l] += __shfl_xor_sync(0xffffffffu, pb[l], off);
            }
        }

        // scalar alpha recurrences
        float aA = 1.0f, aB = 1.0f;
#pragma unroll
        for (int l = 0; l < CN_L; ++l) {
            aA = fmaf(aA, pa[l], aA + c[l]);
            aB = fmaf(aB, pb[l], aB + c[l]);
        }

        // epilogue: beta chunk loaded once, used by both rows, then dead
#pragma unroll
        for (int i = 0; i < 4; ++i) {
            const float4 bt = sbeta[i * 8 + li];
            if (okA) {
                float4 o;
                o.x = fmaf(xa[i].x, aA, bt.x);
                o.y = fmaf(xa[i].y, aA, bt.y);
                o.z = fmaf(xa[i].z, aA, bt.z);
                o.w = fmaf(xa[i].w, aA, bt.w);
                __stcs(&out[rA * 32 + i * 8 + li], o);
            }
            if (okB) {
                float4 o;
                o.x = fmaf(xb[i].x, aB, bt.x);
                o.y = fmaf(xb[i].y, aB, bt.y);
                o.z = fmaf(xb[i].z, aB, bt.z);
                o.w = fmaf(xb[i].w, aB, bt.w);
                __stcs(&out[rB * 32 + i * 8 + li], o);
            }
        }
    }
}

extern "C" void kernel_launch(void* const* d_in, const int* in_sizes, int n_in,
                              void* d_out, int out_size)
{
    const float* x = (const float*)d_in[0];   // inputs  [B,128]
    const float* w = (const float*)d_in[1];   // kernels [L,128,1]
    const float* b = (const float*)d_in[2];   // biases  [L,128,1]
    float* out = (float*)d_out;

    const int B = in_sizes[0] / CN_D;                        // 500000
    const long long warps_needed = ((long long)B + 15) / 16; // 31250
    const int warps_per_block = 256 / 32;
    const int grid = (int)((warps_needed + warps_per_block - 1) / warps_per_block);

    crossnet_kernel<<<grid, 256>>>(
        reinterpret_cast<const float4*>(x),
        reinterpret_cast<const float4*>(w),
        reinterpret_cast<const float4*>(b),
        reinterpret_cast<float4*>(out), B);
}